// round 7
// baseline (speedup 1.0000x reference)
#include <cuda_runtime.h>
#include <cstdint>

// Problem constants (fixed by setup_inputs): B=4, N=512, K=27
#define BB 4
#define NN 512
#define KK 27
#define S_ELEMS 28311552u          // B*N*N*K
#define GROUPS (S_ELEMS / 4u)      // 7,077,888 = 27648 * 256 exactly
#define TPB 256u

// Output layout (concatenated, reference return order):
//   [0, S)        distances    [B,N,N,K]
//   [S, 4S)       distance_vec [B,N,N,K,3]
//   [4S, 5S)      mask (1.0/0.0) [B,N,N,K]
//   [5S, 5S+324)  offset_cart  [B,K,3]

__device__ __forceinline__ void offset_for(const float* __restrict__ cell,
                                           unsigned b, unsigned k,
                                           float& ox, float& oy, float& oz) {
    const float f0 = (float)((int)(k / 9u) - 1);
    const float f1 = (float)((int)((k / 3u) % 3u) - 1);
    const float f2 = (float)((int)(k % 3u) - 1);
    const float* c = cell + b * 9u;
    // match jnp rounding: left-to-right adds, no fma
    ox = __fadd_rn(__fadd_rn(__fmul_rn(f0, __ldg(c + 0)), __fmul_rn(f1, __ldg(c + 3))),
                   __fmul_rn(f2, __ldg(c + 6)));
    oy = __fadd_rn(__fadd_rn(__fmul_rn(f0, __ldg(c + 1)), __fmul_rn(f1, __ldg(c + 4))),
                   __fmul_rn(f2, __ldg(c + 7)));
    oz = __fadd_rn(__fadd_rn(__fmul_rn(f0, __ldg(c + 2)), __fmul_rn(f1, __ldg(c + 5))),
                   __fmul_rn(f2, __ldg(c + 8)));
}

__global__ __launch_bounds__(TPB)
void pbc_edges_kernel(const float* __restrict__ pos,
                      const float* __restrict__ cell,
                      float* __restrict__ out) {
    // Padded (float4-stride) offset table: one LDS.128 fetches (ox,oy,oz).
    __shared__ float4 s_off[BB * KK];
    if (threadIdx.x < BB * KK) {
        const unsigned b = threadIdx.x / KK;
        const unsigned k = threadIdx.x % KK;
        float ox, oy, oz;
        offset_for(cell, b, k, ox, oy, oz);
        s_off[threadIdx.x] = make_float4(ox, oy, oz, 0.0f);
        // Fused offset_cart output: block 0 writes the tiny [B,K,3] tail.
        if (blockIdx.x == 0) {
            float* dst = out + 5ull * S_ELEMS + (size_t)threadIdx.x * 3u;
            dst[0] = ox;
            dst[1] = oy;
            dst[2] = oz;
        }
    }
    __syncthreads();

    const unsigned g = blockIdx.x * TPB + threadIdx.x;
    if (g >= GROUPS) return;
    const unsigned base = g * 4u;

    // Decompose base once. Within a 4-run, t (hence b,i,j) changes at most
    // once, and only if k0 >= 24 — hoist position loads accordingly.
    const unsigned k0 = base % KK;     // single magic multiply
    const unsigned t0 = base / KK;

    const unsigned j0 = t0 & (NN - 1);
    const unsigned i0 = (t0 >> 9) & (NN - 1);
    const unsigned b0 = t0 >> 18;

    const float* pj = pos + ((size_t)b0 * NN + j0) * 3u;
    const float* pi = pos + ((size_t)b0 * NN + i0) * 3u;
    const float pjx0 = __ldg(pj + 0), pjy0 = __ldg(pj + 1), pjz0 = __ldg(pj + 2);
    const float pix0 = __ldg(pi + 0), piy0 = __ldg(pi + 1), piz0 = __ldg(pi + 2);

    float pjx1 = pjx0, pjy1 = pjy0, pjz1 = pjz0;
    float pix1 = pix0, piy1 = piy0, piz1 = piz0;
    unsigned b1 = b0;
    if (k0 >= KK - 3u) {               // wrap occurs inside this 4-run
        const unsigned t1 = t0 + 1u;
        const unsigned j1 = t1 & (NN - 1);
        const unsigned i1 = (t1 >> 9) & (NN - 1);
        b1 = t1 >> 18;
        const float* pj1p = pos + ((size_t)b1 * NN + j1) * 3u;
        const float* pi1p = pos + ((size_t)b1 * NN + i1) * 3u;
        pjx1 = __ldg(pj1p + 0); pjy1 = __ldg(pj1p + 1); pjz1 = __ldg(pj1p + 2);
        pix1 = __ldg(pi1p + 0); piy1 = __ldg(pi1p + 1); piz1 = __ldg(pi1p + 2);
    }

    float d[4], mf[4], vxm[4], vym[4], vzm[4];

#pragma unroll
    for (int e = 0; e < 4; ++e) {
        const unsigned kk = k0 + (unsigned)e;
        const bool second = (kk >= KK);
        const unsigned k = second ? kk - KK : kk;
        const unsigned bsel = second ? b1 : b0;

        const float4 off = s_off[bsel * KK + k];
        const float ox = off.x, oy = off.y, oz = off.z;

        const float pjx = second ? pjx1 : pjx0;
        const float pjy = second ? pjy1 : pjy0;
        const float pjz = second ? pjz1 : pjz0;
        const float pix = second ? pix1 : pix0;
        const float piy = second ? piy1 : piy0;
        const float piz = second ? piz1 : piz0;

        // vec = (pos_j + offset) - pos_i  (reference add order, no fma)
        const float vx = __fadd_rn(__fadd_rn(pjx, ox), -pix);
        const float vy = __fadd_rn(__fadd_rn(pjy, oy), -piy);
        const float vz = __fadd_rn(__fadd_rn(pjz, oz), -piz);

        const float sq = __fadd_rn(__fadd_rn(__fmul_rn(vx, vx), __fmul_rn(vy, vy)),
                                   __fmul_rn(vz, vz));

        const bool m = (sq > 1e-8f) & (sq <= 25.0f);
        mf[e] = m ? 1.0f : 0.0f;
        d[e]  = m ? __fsqrt_rn(sq) : 0.0f;
        vxm[e] = m ? vx : 0.0f;
        vym[e] = m ? vy : 0.0f;
        vzm[e] = m ? vz : 0.0f;
    }

    // Fully coalesced 128-bit streaming stores.
    float4* dist4 = (float4*)(out + base);
    __stcs(dist4, make_float4(d[0], d[1], d[2], d[3]));

    float4* mask4 = (float4*)(out + 4ull * S_ELEMS + base);
    __stcs(mask4, make_float4(mf[0], mf[1], mf[2], mf[3]));

    // distance_vec: 12 contiguous floats per thread, base*3 is 4-aligned.
    float4* vec4 = (float4*)(out + (size_t)S_ELEMS + (size_t)base * 3u);
    __stcs(vec4 + 0, make_float4(vxm[0], vym[0], vzm[0], vxm[1]));
    __stcs(vec4 + 1, make_float4(vym[1], vzm[1], vxm[2], vym[2]));
    __stcs(vec4 + 2, make_float4(vzm[2], vxm[3], vym[3], vzm[3]));
}

extern "C" void kernel_launch(void* const* d_in, const int* in_sizes, int n_in,
                              void* d_out, int out_size) {
    const float* pos  = (const float*)d_in[0];   // [B,N,3]
    const float* cell = (const float*)d_in[1];   // [B,3,3]
    float* out = (float*)d_out;

    const unsigned blocks = GROUPS / TPB;        // exact: 27648
    pbc_edges_kernel<<<blocks, TPB>>>(pos, cell, out);
}